// round 1
// baseline (speedup 1.0000x reference)
#include <cuda_runtime.h>

// y[..., 2k]   = T[k,0,0]*x[2k] + T[k,0,1]*x[2k+1]
// y[..., 2k+1] = T[k,1,0]*x[2k] + T[k,1,1]*x[2k+1]
// x: (4, 2048, 4096) fp32, twiddle: (2048, 2, 2) fp32.
// One thread = one float4 = 2 adjacent pairs. Row length 4096 floats = 1024 float4.

__global__ __launch_bounds__(256) void butterfly_kernel(
    const float4* __restrict__ x,
    const float4* __restrict__ tw,   // tw[k] = (t00, t01, t10, t11)
    float4* __restrict__ y,
    int n4)
{
    int i = blockIdx.x * blockDim.x + threadIdx.x;
    if (i >= n4) return;

    float4 v = x[i];

    // within-row float4 offset -> pair index of first pair in this float4
    int off  = i & 1023;       // 4096/4 = 1024 float4 per row
    int pair = off << 1;       // first pair index (covers pairs pair, pair+1)

    float4 t0 = __ldg(&tw[pair]);
    float4 t1 = __ldg(&tw[pair + 1]);

    float4 r;
    r.x = fmaf(t0.x, v.x, t0.y * v.y);
    r.y = fmaf(t0.z, v.x, t0.w * v.y);
    r.z = fmaf(t1.x, v.z, t1.y * v.w);
    r.w = fmaf(t1.z, v.z, t1.w * v.w);

    y[i] = r;
}

extern "C" void kernel_launch(void* const* d_in, const int* in_sizes, int n_in,
                              void* d_out, int out_size)
{
    const float4* x  = (const float4*)d_in[0];
    const float4* tw = (const float4*)d_in[1];
    float4* y        = (float4*)d_out;

    int n4 = out_size / 4;            // total float4 elements = 8,388,608
    int threads = 256;
    int blocks  = (n4 + threads - 1) / threads;

    butterfly_kernel<<<blocks, threads>>>(x, tw, y, n4);
}

// round 2
// speedup vs baseline: 1.0471x; 1.0471x over previous
#include <cuda_runtime.h>

// y[..., 2k]   = T[k,0,0]*x[2k] + T[k,0,1]*x[2k+1]
// y[..., 2k+1] = T[k,1,0]*x[2k] + T[k,1,1]*x[2k+1]
// x: (4, 2048, 4096) fp32, twiddle: (2048, 2, 2) fp32.
//
// One block = one 4096-float row = 1024 float4. 256 threads x 4 float4 each.
// Front-batched loads (12 LDG.128/thread) for deep MLP; streaming hints on
// x/y so the 32 KiB twiddle stays resident in L1/L2.

__global__ __launch_bounds__(256) void butterfly_kernel(
    const float4* __restrict__ x,
    const float4* __restrict__ tw,   // tw[k] = (t00, t01, t10, t11)
    float4* __restrict__ y)
{
    const int t    = threadIdx.x;
    const int base = blockIdx.x << 10;          // row * 1024 float4

    float4 v[4], t0[4], t1[4];

    // Front-batch all independent loads: 4 streaming x-loads...
#pragma unroll
    for (int u = 0; u < 4; u++) {
        v[u] = __ldcs(&x[base + t + (u << 8)]);
    }
    // ...then 8 cached twiddle loads (L1/L2 resident after first wave).
#pragma unroll
    for (int u = 0; u < 4; u++) {
        const int pair = (t + (u << 8)) << 1;
        t0[u] = __ldg(&tw[pair]);
        t1[u] = __ldg(&tw[pair + 1]);
    }

#pragma unroll
    for (int u = 0; u < 4; u++) {
        float4 r;
        r.x = fmaf(t0[u].x, v[u].x, t0[u].y * v[u].y);
        r.y = fmaf(t0[u].z, v[u].x, t0[u].w * v[u].y);
        r.z = fmaf(t1[u].x, v[u].z, t1[u].y * v[u].w);
        r.w = fmaf(t1[u].z, v[u].z, t1[u].w * v[u].w);
        __stcs(&y[base + t + (u << 8)], r);
    }
}

extern "C" void kernel_launch(void* const* d_in, const int* in_sizes, int n_in,
                              void* d_out, int out_size)
{
    const float4* x  = (const float4*)d_in[0];
    const float4* tw = (const float4*)d_in[1];
    float4* y        = (float4*)d_out;

    const int n4    = out_size / 4;     // total float4 = 8,388,608
    const int rows  = n4 >> 10;         // 1024 float4 per row -> 8192 blocks

    butterfly_kernel<<<rows, 256>>>(x, tw, y);
}